// round 13
// baseline (speedup 1.0000x reference)
#include <cuda_runtime.h>
#include <cuda_bf16.h>
#include <math.h>

// ---------------- problem dims ----------------
#define NB 2
#define HH 64
#define WW 64
#define DD 256
#define SS 16
#define NHD 4
#define HDIM 64
#define MLPH 1024
#define NPOS (NB*HH*WW)          // 8192
#define NKV  (NPOS*SS)           // 131072

// ---------------- scratch (device globals; no allocations allowed) -------
__device__ __align__(256) float g_Wqk [DD * 4 * DD];          // folded Wq·Wk^T [256,1024]
__device__ __align__(256) float g_Wvo [4 * DD * DD];          // folded Wv·Wo   [1024,256]
__device__ __align__(256) float g_bqk [4 * DD];               // folded bq·Wk^T [1024]
__device__ __align__(256) float g_bvo [DD];                   // folded bo+bv·Wo [256]
__device__ __align__(256) float g_qk  [(size_t)NPOS * 4 * DD];// hs·Wqk [8192,1024]
__device__ __align__(256) float g_pkv [(size_t)NPOS * 4 * DD];// p-weighted kv [8192,1024]
__device__ __align__(256) float g_o   [(size_t)NPOS * DD];    // attn out [8192,256]
__device__ __align__(256) float g_x   [(size_t)NPOS * DD];    // post-LN1
__device__ __align__(256) float g_h1  [(size_t)NPOS * MLPH];  // mlp hidden
__device__ __align__(256) float g_y   [(size_t)NPOS * DD];    // pre-LN2

// ---------------- helpers ----------------
__device__ __forceinline__ float blk_sum256(float v, float* red) {
    int t = threadIdx.x;
    red[t] = v; __syncthreads();
    #pragma unroll
    for (int o = 128; o > 0; o >>= 1) {
        if (t < o) red[t] += red[t + o];
        __syncthreads();
    }
    float r = red[0]; __syncthreads();
    return r;
}

__device__ __forceinline__ float gelu_tanh(float x) {
    const float c = 0.7978845608028654f;
    float t = tanhf(c * (x + 0.044715f * x * x * x));
    return 0.5f * x * (1.f + t);
}

__device__ __forceinline__ unsigned f2tf32(float v) {
    unsigned u;
    asm("cvt.rna.tf32.f32 %0, %1;" : "=r"(u) : "f"(v));
    return u;
}

__device__ __forceinline__ void mma_tf32(float c[4], const unsigned a[4],
                                         const unsigned b[2]) {
    asm volatile(
        "mma.sync.aligned.m16n8k8.row.col.f32.tf32.tf32.f32 "
        "{%0,%1,%2,%3}, {%4,%5,%6,%7}, {%8,%9}, {%0,%1,%2,%3};\n"
        : "+f"(c[0]), "+f"(c[1]), "+f"(c[2]), "+f"(c[3])
        : "r"(a[0]), "r"(a[1]), "r"(a[2]), "r"(a[3]), "r"(b[0]), "r"(b[1]));
}

// ============================================================
// K_fold_qk (grid 260):
//  blocks 0..255 : Wqk[dd][a*256+d] = sum_e Wq[dd,a*64+e]*Wk[d*256+a*64+e]
//  blocks 256..259: bqk[a*256+d]    = sum_e bq[a*64+e]  *Wk[d*256+a*64+e]
// ============================================================
__global__ __launch_bounds__(256)
void k_fold_qk(const float* __restrict__ Wq, const float* __restrict__ Wk,
               const float* __restrict__ bq) {
    __shared__ float sA[256];
    int t = threadIdx.x, b = blockIdx.x;
    if (b < 256) {
        sA[t] = Wq[b * 256 + t];
        __syncthreads();
        #pragma unroll
        for (int a = 0; a < 4; ++a) {
            const float* wk = &Wk[t * 256 + a * 64];
            const float* wq = &sA[a * 64];
            float acc = 0.f;
            #pragma unroll 16
            for (int e = 0; e < 64; ++e) acc += wq[e] * wk[e];
            g_Wqk[b * 1024 + a * 256 + t] = acc;
        }
    } else {
        int a = b - 256;
        const float* wk = &Wk[t * 256 + a * 64];
        const float* bqp = &bq[a * 64];
        float acc = 0.f;
        #pragma unroll 16
        for (int e = 0; e < 64; ++e) acc += bqp[e] * wk[e];
        g_bqk[a * 256 + t] = acc;
    }
}

// ============================================================
// K_fold_vo (grid 1025):
//  blocks 0..1023 (a,dd): Wvo[a*256+dd][d] = sum_e Wv[dd,a*64+e]*Wo[(a*64+e)*256+d]
//  block 1024          : bvo[d] = bo[d] + sum_ae bv[ae]*Wo[ae*256+d]
// ============================================================
__global__ __launch_bounds__(256)
void k_fold_vo(const float* __restrict__ Wv, const float* __restrict__ Wo,
               const float* __restrict__ bv, const float* __restrict__ bo) {
    int t = threadIdx.x, b = blockIdx.x;
    if (b < 1024) {
        int a = b >> 8, dd = b & 255;
        const float* wo = &Wo[(a * 64) * 256 + t];
        const float* wv = &Wv[dd * 256 + a * 64];
        float acc = 0.f;
        #pragma unroll 16
        for (int e = 0; e < 64; ++e) acc += wv[e] * wo[e * 256];
        g_Wvo[(a * 256 + dd) * 256 + t] = acc;
    } else {
        float acc = bo[t];
        #pragma unroll 8
        for (int ae = 0; ae < 256; ++ae) acc += bv[ae] * Wo[ae * 256 + t];
        g_bvo[t] = acc;
    }
}

// ============================================================
// K_sample_core: offsets + bilinear gather (kv in SMEM) + scores
//                + softmax + pkv.   ONE position per block, 256 thr.
// ============================================================
__global__ __launch_bounds__(256)
void k_sample_core(const float* __restrict__ hs, const float* __restrict__ emb,
                   const float* __restrict__ Woff, const float* __restrict__ boff,
                   const float* __restrict__ Wkvp, const float* __restrict__ bkvp) {
    __shared__ float s_kv[16 * 258];
    __shared__ float s_qk[1024];
    __shared__ float s_red[256];
    __shared__ float s_off[32];
    __shared__ float s_w[SS][4];
    __shared__ int   s_idx[SS][4];
    __shared__ float s_sc[64];
    __shared__ float s_p[64];
    int t = threadIdx.x;
    int p = blockIdx.x;
    int n  = p >> 12;
    int iy = (p >> 6) & 63, jx = p & 63;
    int w = t >> 5, lane = t & 31;

    // qk row for this position
    #pragma unroll
    for (int i = 0; i < 4; ++i)
        s_qk[i * 256 + t] = g_qk[(size_t)p * 1024 + i * 256 + t];

    // offsets: segment-parallel dot; warp w covers d in [w*32, w*32+32), lane = out col
    {
        const float* hp = &hs[(size_t)p * 256 + w * 32];
        const float* wo = &Woff[(w * 32) * 32 + lane];
        float acc = 0.f;
        #pragma unroll
        for (int i = 0; i < 32; ++i) acc += hp[i] * wo[i * 32];
        s_red[t] = acc;
    }
    __syncthreads();
    if (t < 32) {
        float acc = boff[t];
        #pragma unroll
        for (int s = 0; s < 8; ++s) acc += s_red[s * 32 + t];
        float sg = 1.f / (1.f + expf(-acc));
        s_off[t] = 60.f * sg - 30.f;
    }
    __syncthreads();

    if (t < SS) {
        int s = t;
        float y = fminf(fmaxf((float)iy + s_off[2*s    ], 0.f), 63.f);
        float x = fminf(fmaxf((float)jx + s_off[2*s + 1], 0.f), 63.f);
        float y0f = floorf(y), x0f = floorf(x);
        int y0 = (int)y0f, x0 = (int)x0f;
        int y1 = min(y0 + 1, 63), x1 = min(x0 + 1, 63);
        float wy = y - y0f, wx = x - x0f;
        s_w[s][0] = (1.f - wy) * (1.f - wx);
        s_w[s][1] = (1.f - wy) * wx;
        s_w[s][2] = wy * (1.f - wx);
        s_w[s][3] = wy * wx;
        int base = n * 4096;
        s_idx[s][0] = (base + y0 * 64 + x0) * DD;
        s_idx[s][1] = (base + y0 * 64 + x1) * DD;
        s_idx[s][2] = (base + y1 * 64 + x0) * DD;
        s_idx[s][3] = (base + y1 * 64 + x1) * DD;
    }
    __syncthreads();

    // gather kv + offset embedding -> SMEM only
    {
        float wkvp0 = Wkvp[t];
        float wkvp1 = Wkvp[DD + t];
        float bkv   = bkvp[t];
        #pragma unroll 4
        for (int s = 0; s < SS; ++s) {
            float v = s_w[s][0] * emb[s_idx[s][0] + t]
                    + s_w[s][1] * emb[s_idx[s][1] + t]
                    + s_w[s][2] * emb[s_idx[s][2] + t]
                    + s_w[s][3] * emb[s_idx[s][3] + t];
            v += s_off[2*s] * wkvp0 + s_off[2*s + 1] * wkvp1 + bkv;
            s_kv[s * 258 + t] = v;
        }
    }
    __syncthreads();

    // scores: 64 (a,s) pairs, 4 lanes per pair, interleaved d = sub + 4*i
    {
        int pair = t >> 2, sub = t & 3;
        int a = pair >> 4, s = pair & 15;
        const float* kvp = &s_kv[s * 258 + sub];
        const float* qkp = &s_qk[a * 256 + sub];
        float acc = 0.f;
        #pragma unroll 16
        for (int i = 0; i < 64; ++i) acc += qkp[i * 4] * kvp[i * 4];
        acc += __shfl_xor_sync(0xffffffffu, acc, 1);
        acc += __shfl_xor_sync(0xffffffffu, acc, 2);
        if (sub == 0) s_sc[pair] = acc * 0.125f;
    }
    __syncthreads();

    if (t < 4) {
        float mx = -1e30f;
        #pragma unroll
        for (int s = 0; s < 16; ++s) mx = fmaxf(mx, s_sc[t * 16 + s]);
        float sum = 0.f;
        float e[16];
        #pragma unroll
        for (int s = 0; s < 16; ++s) { e[s] = expf(s_sc[t * 16 + s] - mx); sum += e[s]; }
        float inv = 1.f / sum;
        #pragma unroll
        for (int s = 0; s < 16; ++s) s_p[t * 16 + s] = e[s] * inv;
    }
    __syncthreads();

    #pragma unroll
    for (int a = 0; a < 4; ++a) {
        float acc = 0.f;
        #pragma unroll
        for (int s = 0; s < 16; ++s)
            acc += s_p[a * 16 + s] * s_kv[s * 258 + t];
        g_pkv[(size_t)p * 1024 + a * 256 + t] = acc;
    }
}

// ============================================================
// TF32 tensor-core GEMM (mma.sync m16n8k8) — simple smem staging.
// 128x64 block tile, BK=16. 256 thr = 8 warps (4x2), warp tile 32x32.
// EPI: 0 = +bias, 1 = gelu(+bias), 2 = +bias+res
// ============================================================
template<int KTOT, int EPI>
__global__ __launch_bounds__(256)
void gemm_tf32(const float* __restrict__ A, const float* __restrict__ B,
               float* __restrict__ C, int N,
               const float* __restrict__ bias, const float* __restrict__ res) {
    __shared__ float As[16][132];
    __shared__ float Bs[16][68];
    int t = threadIdx.x, lane = t & 31, wid = t >> 5;
    int wm = wid >> 1, wn = wid & 1;           // 4 x 2 warp grid
    long rowBase = (long)blockIdx.x * 128;
    int  colBase = blockIdx.y * 64;
    float c[2][4][4] = {};

    int am = t >> 1, ak = (t & 1) * 8;          // A staging: row am, 8 k's
    int bk = t >> 4, bn = (t & 15) * 4;         // B staging: row bk, 4 n's
    int r = lane >> 2, kq = lane & 3;           // fragment row/col within warp

    #pragma unroll 1
    for (int k0 = 0; k0 < KTOT; k0 += 16) {
        {
            const float* arow = &A[(rowBase + am) * (long)KTOT + k0 + ak];
            float4 a0 = *(const float4*)(arow);
            float4 a1 = *(const float4*)(arow + 4);
            As[ak + 0][am] = a0.x; As[ak + 1][am] = a0.y;
            As[ak + 2][am] = a0.z; As[ak + 3][am] = a0.w;
            As[ak + 4][am] = a1.x; As[ak + 5][am] = a1.y;
            As[ak + 6][am] = a1.z; As[ak + 7][am] = a1.w;
            *(float4*)&Bs[bk][bn] =
                *(const float4*)&B[(long)(k0 + bk) * N + colBase + bn];
        }
        __syncthreads();
        #pragma unroll
        for (int ks = 0; ks < 2; ++ks) {
            int kb = ks * 8;
            unsigned af[2][4], bf[4][2];
            #pragma unroll
            for (int i = 0; i < 2; ++i) {
                int m0 = wm * 32 + i * 16;
                af[i][0] = f2tf32(As[kb + kq    ][m0 + r    ]);
                af[i][1] = f2tf32(As[kb + kq    ][m0 + r + 8]);
                af[i][2] = f2tf32(As[kb + kq + 4][m0 + r    ]);
                af[i][3] = f2tf32(As[kb + kq + 4][m0 + r + 8]);
            }
            #pragma unroll
            for (int j = 0; j < 4; ++j) {
                int n0 = wn * 32 + j * 8;
                bf[j][0] = f2tf32(Bs[kb + kq    ][n0 + r]);
                bf[j][1] = f2tf32(Bs[kb + kq + 4][n0 + r]);
            }
            #pragma unroll
            for (int i = 0; i < 2; ++i)
                #pragma unroll
                for (int j = 0; j < 4; ++j)
                    mma_tf32(c[i][j], af[i], bf[j]);
        }
        __syncthreads();
    }

    // ---- epilogue: c[i][j][e] -> C[row][col] ----
    #pragma unroll
    for (int i = 0; i < 2; ++i) {
        #pragma unroll
        for (int j = 0; j < 4; ++j) {
            long row0 = rowBase + wm * 32 + i * 16 + r;
            int  col0 = colBase + wn * 32 + j * 8 + 2 * kq;
            #pragma unroll
            for (int e = 0; e < 4; ++e) {
                long row = row0 + (e >> 1) * 8;
                int  col = col0 + (e & 1);
                float v = c[i][j][e] + bias[col];
                if (EPI == 1) v = gelu_tanh(v);
                if (EPI == 2) v += res[row * N + col];
                C[row * N + col] = v;
            }
        }
    }
}

// ============================================================
// K_ln: out = LN(xin (+ addin)) * sc + bi
// ============================================================
__global__ __launch_bounds__(256)
void k_ln(const float* __restrict__ xin, const float* __restrict__ addin,
          const float* __restrict__ sc, const float* __restrict__ bi,
          float* __restrict__ out) {
    __shared__ float red[256];
    int t = threadIdx.x;
    for (int pp = 0; pp < 4; ++pp) {
        size_t p = (size_t)blockIdx.x * 4 + pp;
        float x = xin[p * 256 + t];
        if (addin) x += addin[p * 256 + t];
        float sum  = blk_sum256(x, red);
        float sum2 = blk_sum256(x * x, red);
        float mean = sum * (1.f / 256.f);
        float var  = sum2 * (1.f / 256.f) - mean * mean;
        out[p * 256 + t] = (x - mean) * rsqrtf(var + 1e-6f) * sc[t] + bi[t];
    }
}

// ============================================================
extern "C" void kernel_launch(void* const* d_in, const int* in_sizes, int n_in,
                              void* d_out, int out_size) {
    const float* hs    = (const float*)d_in[0];
    const float* emb   = (const float*)d_in[1];
    const float* Woff  = (const float*)d_in[2];
    const float* boff  = (const float*)d_in[3];
    const float* Wkvp  = (const float*)d_in[4];
    const float* bkvp  = (const float*)d_in[5];
    const float* Wq    = (const float*)d_in[6];
    const float* bq    = (const float*)d_in[7];
    const float* Wk    = (const float*)d_in[8];
    const float* bk    = (const float*)d_in[9];   (void)bk; // softmax-invariant, folded out
    const float* Wv    = (const float*)d_in[10];
    const float* bv    = (const float*)d_in[11];
    const float* Wo    = (const float*)d_in[12];
    const float* bo    = (const float*)d_in[13];
    const float* ln1s  = (const float*)d_in[14];
    const float* ln1b  = (const float*)d_in[15];
    const float* ln2s  = (const float*)d_in[16];
    const float* ln2b  = (const float*)d_in[17];
    const float* W1    = (const float*)d_in[18];
    const float* b1    = (const float*)d_in[19];
    const float* W2    = (const float*)d_in[20];
    const float* b2    = (const float*)d_in[21];
    float* out = (float*)d_out;

    float *p_Wqk, *p_Wvo, *p_bqk, *p_bvo;
    float *p_qk, *p_pkv, *p_o, *p_x, *p_h1, *p_y;
    cudaGetSymbolAddress((void**)&p_Wqk,  g_Wqk);
    cudaGetSymbolAddress((void**)&p_Wvo,  g_Wvo);
    cudaGetSymbolAddress((void**)&p_bqk,  g_bqk);
    cudaGetSymbolAddress((void**)&p_bvo,  g_bvo);
    cudaGetSymbolAddress((void**)&p_qk,   g_qk);
    cudaGetSymbolAddress((void**)&p_pkv,  g_pkv);
    cudaGetSymbolAddress((void**)&p_o,    g_o);
    cudaGetSymbolAddress((void**)&p_x,    g_x);
    cudaGetSymbolAddress((void**)&p_h1,   g_h1);
    cudaGetSymbolAddress((void**)&p_y,    g_y);

    // ---- one-time weight folding (2 wide parallel kernels) ----
    k_fold_qk<<<260, 256>>>(Wq, Wk, bq);
    k_fold_vo<<<1025, 256>>>(Wv, Wo, bv, bo);

    // ---- main pipeline ----
    // qk = hs @ Wqk + bqk   [tf32]
    gemm_tf32<256, 0><<<dim3(64, 16), 256>>>(hs, p_Wqk, p_qk, 1024, p_bqk, nullptr);
    // fused: offsets + gather kv (SMEM) + scores + softmax + pkv  (1 pos/block)
    k_sample_core<<<NPOS, 256>>>(hs, emb, Woff, boff, Wkvp, bkvp);
    // o = pkv @ Wvo + bvo   [tf32]
    gemm_tf32<1024, 0><<<dim3(64, 4), 256>>>(p_pkv, p_Wvo, p_o, 256, p_bvo, nullptr);
    // x = LN1(hs + o)
    k_ln<<<NPOS / 4, 256>>>(hs, p_o, ln1s, ln1b, p_x);
    // h1 = gelu(x @ W1 + b1)   [tf32]
    gemm_tf32<256, 1><<<dim3(64, 16), 256>>>(p_x, W1, p_h1, 1024, b1, nullptr);
    // y = x + h1 @ W2 + b2     [tf32]
    gemm_tf32<1024, 2><<<dim3(64, 4), 256>>>(p_h1, W2, p_y, 256, b2, p_x);
    // out = LN2(y)
    k_ln<<<NPOS / 4, 256>>>(p_y, nullptr, ln2s, ln2b, out);
}